// round 16
// baseline (speedup 1.0000x reference)
#include <cuda_runtime.h>
#include <cstddef>
#include <cstdint>

// Problem constants
constexpr int B_ = 4, C_ = 16, S_ = 512, E_ = 512, H_ = 8, HD_ = 64;
constexpr int TOKENS_ = B_ * C_ * S_;                         // 32768
constexpr size_t OUT_ELEMS  = (size_t)TOKENS_ * E_;           // 16,777,216
constexpr size_t ATTN_ELEMS = (size_t)B_ * H_ * C_ * S_ * S_; // 134,217,728

// ---------------------------------------------------------------------------
// Scratch (__device__ globals: allocation APIs are banned)
// ---------------------------------------------------------------------------
__device__ __align__(128) float g_q[OUT_ELEMS];
__device__ __align__(128) float g_k[OUT_ELEMS];
__device__ __align__(128) float g_v[OUT_ELEMS];
__device__ __align__(128) float g_vt[OUT_ELEMS];   // per-(b,c) transposed V proj
__device__ __align__(128) float g_ctx[OUT_ELEMS];
__device__ __align__(128) float g_attn_fb[ATTN_ELEMS];

// ---------------------------------------------------------------------------
// tf32 helpers (baseline PTX, valid for sm_103 family target)
// ---------------------------------------------------------------------------
__device__ __forceinline__ float to_tf32(float x) {
    float r;
    asm("cvt.rna.tf32.f32 %0, %1;" : "=f"(r) : "f"(x));
    return r;
}
__device__ __forceinline__ float4 tf32x4(float4 v) {
    v.x = to_tf32(v.x); v.y = to_tf32(v.y);
    v.z = to_tf32(v.z); v.w = to_tf32(v.w);
    return v;
}
__device__ __forceinline__ void mma_tf32(float* c, const uint32_t* a, const uint32_t* b) {
    asm volatile(
        "mma.sync.aligned.m16n8k8.row.col.f32.tf32.tf32.f32 "
        "{%0,%1,%2,%3}, {%4,%5,%6,%7}, {%8,%9}, {%0,%1,%2,%3};"
        : "+f"(c[0]), "+f"(c[1]), "+f"(c[2]), "+f"(c[3])
        : "r"(a[0]), "r"(a[1]), "r"(a[2]), "r"(a[3]), "r"(b[0]), "r"(b[1]));
}

// ---------------------------------------------------------------------------
// tf32 mma.sync GEMM (TN): C[M,N] = alpha * A[M,K] @ B[N,K]^T (+ bias[N])
// BM=128, BK=16. BN_=128 -> 512 threads (4x4 warps); BN_=64 -> 256 (4x2).
// Warp tile 32x32 = 2x4 m16n8k8 tiles. Register-prefetch double buffering.
// MODE 0: plain. MODE 1: scores (z=(b*H+h)*C+c head slice of Q/K, out z*S*S).
// MODE 2: ctx (A = attn slab z, B = transposed-V head slice, out head slice).
// ---------------------------------------------------------------------------
constexpr int TBM = 128, TBK = 16;

template <int BN_, int MODE>
__global__ void __launch_bounds__((BN_ == 128) ? 512 : 256)
gemm_mma(const float* __restrict__ Ag, const float* __restrict__ Bg,
         float* __restrict__ Cg, int lda, int ldb, int ldc, int K,
         float alpha, const float* __restrict__ bias)
{
    constexpr int NTH     = (BN_ == 128) ? 512 : 256;
    constexpr int WARPS_N = BN_ / 32;                       // 4 or 2
    constexpr int NLD_A   = (TBM * TBK / 4) / NTH;          // 1 or 2
    constexpr int NLD_B   = (BN_ * TBK / 4) / NTH;          // 1

    __shared__ float As[TBK][TBM + 4];   // [k][m], pitch 132
    __shared__ float Bs[TBK][BN_ + 4];   // [k][n]

    const float* A  = Ag;
    const float* Bm = Bg;
    float* Cp = Cg;
    if (MODE == 1) {
        int z = blockIdx.z;
        int c = z % C_, h = (z / C_) % H_, b = z / (C_ * H_);
        size_t off = ((size_t)(b * C_ + c) * S_) * E_ + (size_t)h * HD_;
        A = Ag + off; Bm = Bg + off;
        Cp = Cg + (size_t)z * S_ * S_;
    }
    if (MODE == 2) {
        int z = blockIdx.z;
        int c = z % C_, h = (z / C_) % H_, b = z / (C_ * H_);
        A  = Ag + (size_t)z * S_ * S_;
        Bm = Bg + ((size_t)(b * C_ + c) * E_ + (size_t)h * HD_) * S_;
        Cp = Cg + (size_t)(b * C_ + c) * S_ * E_ + (size_t)h * HD_;
    }

    const int tid  = threadIdx.x;
    const int wid  = tid >> 5;
    const int lane = tid & 31;
    const int gid  = lane >> 2;     // group of 4
    const int tg   = lane & 3;      // thread in group

    const int warp_m = wid / WARPS_N;   // 0..3
    const int warp_n = wid % WARPS_N;   // 0..WARPS_N-1
    const int wm0 = warp_m * 32;
    const int wn0 = warp_n * 32;

    const int bm = blockIdx.y * TBM;
    const int bn = blockIdx.x * BN_;

    // Global tile-load plan: idx -> row = idx/4, k-chunk = idx%4 (float4)
    const float* pAg[NLD_A]; int arow[NLD_A], ak4[NLD_A];
#pragma unroll
    for (int j = 0; j < NLD_A; j++) {
        int idx = j * NTH + tid;
        arow[j] = idx >> 2; ak4[j] = idx & 3;
        pAg[j] = A + (size_t)(bm + arow[j]) * lda + ak4[j] * 4;
    }
    const float* pBg[NLD_B]; int brow[NLD_B], bk4[NLD_B];
#pragma unroll
    for (int j = 0; j < NLD_B; j++) {
        int idx = j * NTH + tid;
        brow[j] = idx >> 2; bk4[j] = idx & 3;
        pBg[j] = Bm + (size_t)(bn + brow[j]) * ldb + bk4[j] * 4;
    }

    float acc[2][4][4];
#pragma unroll
    for (int mt = 0; mt < 2; mt++)
#pragma unroll
        for (int nt = 0; nt < 4; nt++)
#pragma unroll
            for (int r = 0; r < 4; r++) acc[mt][nt][r] = 0.0f;

    float4 ra[NLD_A], rb[NLD_B];
#pragma unroll
    for (int j = 0; j < NLD_A; j++) ra[j] = *(const float4*)pAg[j];
#pragma unroll
    for (int j = 0; j < NLD_B; j++) rb[j] = *(const float4*)pBg[j];

    const int nslab = K / TBK;
    for (int kt = 0; kt < nslab; kt++) {
        // transposed stores with tf32 rounding
#pragma unroll
        for (int j = 0; j < NLD_A; j++) {
            float4 v = tf32x4(ra[j]);
            int kk = ak4[j] * 4, m = arow[j];
            As[kk + 0][m] = v.x; As[kk + 1][m] = v.y;
            As[kk + 2][m] = v.z; As[kk + 3][m] = v.w;
        }
#pragma unroll
        for (int j = 0; j < NLD_B; j++) {
            float4 v = tf32x4(rb[j]);
            int kk = bk4[j] * 4, n = brow[j];
            Bs[kk + 0][n] = v.x; Bs[kk + 1][n] = v.y;
            Bs[kk + 2][n] = v.z; Bs[kk + 3][n] = v.w;
        }
        __syncthreads();

        if (kt + 1 < nslab) {   // prefetch next slab into registers
#pragma unroll
            for (int j = 0; j < NLD_A; j++)
                ra[j] = *(const float4*)(pAg[j] + (size_t)(kt + 1) * TBK);
#pragma unroll
            for (int j = 0; j < NLD_B; j++)
                rb[j] = *(const float4*)(pBg[j] + (size_t)(kt + 1) * TBK);
        }

#pragma unroll
        for (int ks = 0; ks < TBK; ks += 8) {
            uint32_t af[2][4];
#pragma unroll
            for (int mt = 0; mt < 2; mt++) {
                int m0 = wm0 + mt * 16 + gid;
                af[mt][0] = __float_as_uint(As[ks + tg][m0]);
                af[mt][1] = __float_as_uint(As[ks + tg][m0 + 8]);
                af[mt][2] = __float_as_uint(As[ks + tg + 4][m0]);
                af[mt][3] = __float_as_uint(As[ks + tg + 4][m0 + 8]);
            }
            uint32_t bf[4][2];
#pragma unroll
            for (int nt = 0; nt < 4; nt++) {
                int n0 = wn0 + nt * 8 + gid;
                bf[nt][0] = __float_as_uint(Bs[ks + tg][n0]);
                bf[nt][1] = __float_as_uint(Bs[ks + tg + 4][n0]);
            }
#pragma unroll
            for (int mt = 0; mt < 2; mt++)
#pragma unroll
                for (int nt = 0; nt < 4; nt++)
                    mma_tf32(acc[mt][nt], af[mt], bf[nt]);
        }
        __syncthreads();
    }

    // Epilogue: c0/c1 -> (row, 2tg), (row, 2tg+1); c2/c3 -> row+8
#pragma unroll
    for (int mt = 0; mt < 2; mt++) {
#pragma unroll
        for (int nt = 0; nt < 4; nt++) {
            int row = bm + wm0 + mt * 16 + gid;
            int col = bn + wn0 + nt * 8 + tg * 2;
            float2 bb = make_float2(0.0f, 0.0f);
            if (bias) bb = *(const float2*)(bias + col);
            float2 v0, v1;
            v0.x = acc[mt][nt][0] * alpha + bb.x;
            v0.y = acc[mt][nt][1] * alpha + bb.y;
            v1.x = acc[mt][nt][2] * alpha + bb.x;
            v1.y = acc[mt][nt][3] * alpha + bb.y;
            *(float2*)(Cp + (size_t)row * ldc + col)       = v0;
            *(float2*)(Cp + (size_t)(row + 8) * ldc + col) = v1;
        }
    }
}

// ---------------------------------------------------------------------------
// Per-(b,c) 512x512 transpose of the V projection (token-major -> [e][s])
// so the ctx GEMM sees a K-major (TN) B operand.
// ---------------------------------------------------------------------------
__global__ void transpose512(const float* __restrict__ in, float* __restrict__ out)
{
    __shared__ float t[32][33];
    const size_t base = (size_t)blockIdx.z * 512 * 512;
    const float* I = in + base;
    float* O = out + base;
    int x = blockIdx.x * 32 + threadIdx.x;   // e
    int y = blockIdx.y * 32 + threadIdx.y;   // s
#pragma unroll
    for (int i = 0; i < 32; i += 8)
        t[threadIdx.y + i][threadIdx.x] = I[(size_t)(y + i) * 512 + x];
    __syncthreads();
    int x2 = blockIdx.y * 32 + threadIdx.x;  // s
    int y2 = blockIdx.x * 32 + threadIdx.y;  // e
#pragma unroll
    for (int i = 0; i < 32; i += 8)
        O[(size_t)(y2 + i) * 512 + x2] = t[threadIdx.x][threadIdx.y + i];
}

// ---------------------------------------------------------------------------
// Row softmax, in place, rows of exactly 512 floats. One warp per row.
// ---------------------------------------------------------------------------
__global__ void softmax_rows(float* __restrict__ attn)
{
    const int warp = (blockIdx.x * blockDim.x + threadIdx.x) >> 5;
    const int lane = threadIdx.x & 31;
    float* row = attn + (size_t)warp * S_;

    float4 v[4];
    float mx = -3.0e38f;
#pragma unroll
    for (int i = 0; i < 4; i++) {
        v[i] = *(const float4*)(row + (size_t)(lane + 32 * i) * 4);
        mx = fmaxf(mx, fmaxf(fmaxf(v[i].x, v[i].y), fmaxf(v[i].z, v[i].w)));
    }
#pragma unroll
    for (int s = 16; s > 0; s >>= 1)
        mx = fmaxf(mx, __shfl_xor_sync(0xffffffffu, mx, s));

    float sum = 0.0f;
#pragma unroll
    for (int i = 0; i < 4; i++) {
        v[i].x = __expf(v[i].x - mx); v[i].y = __expf(v[i].y - mx);
        v[i].z = __expf(v[i].z - mx); v[i].w = __expf(v[i].w - mx);
        sum += v[i].x + v[i].y + v[i].z + v[i].w;
    }
#pragma unroll
    for (int s = 16; s > 0; s >>= 1)
        sum += __shfl_xor_sync(0xffffffffu, sum, s);

    const float inv = 1.0f / sum;
#pragma unroll
    for (int i = 0; i < 4; i++) {
        v[i].x *= inv; v[i].y *= inv; v[i].z *= inv; v[i].w *= inv;
        *(float4*)(row + (size_t)(lane + 32 * i) * 4) = v[i];
    }
}

// ---------------------------------------------------------------------------
// Launch (graph-capturable: kernel launches only)
// ---------------------------------------------------------------------------
extern "C" void kernel_launch(void* const* d_in, const int* in_sizes, int n_in,
                              void* d_out, int out_size)
{
    const float* q  = (const float*)d_in[0];
    const float* k  = (const float*)d_in[1];
    const float* v  = (const float*)d_in[2];
    const float* Wq = (const float*)d_in[3];
    const float* bq = (const float*)d_in[4];
    const float* Wk = (const float*)d_in[5];
    const float* bk = (const float*)d_in[6];
    const float* Wv = (const float*)d_in[7];
    const float* bv = (const float*)d_in[8];
    const float* Wo = (const float*)d_in[9];
    const float* bo = (const float*)d_in[10];
    float* out = (float*)d_out;

    float *gq, *gk, *gv, *gvt, *gctx, *gfb;
    cudaGetSymbolAddress((void**)&gq,   g_q);
    cudaGetSymbolAddress((void**)&gk,   g_k);
    cudaGetSymbolAddress((void**)&gv,   g_v);
    cudaGetSymbolAddress((void**)&gvt,  g_vt);
    cudaGetSymbolAddress((void**)&gctx, g_ctx);
    cudaGetSymbolAddress((void**)&gfb,  g_attn_fb);

    float* attn = ((size_t)out_size >= OUT_ELEMS + ATTN_ELEMS)
                      ? (out + OUT_ELEMS) : gfb;

    // 1-3) Q/K/V projections: (32768 x 512) = X @ W^T + b
    dim3 gproj(E_ / 128, TOKENS_ / TBM, 1);
    gemm_mma<128, 0><<<gproj, 512>>>(q, Wq, gq, E_, E_, E_, E_, 1.0f, bq);
    gemm_mma<128, 0><<<gproj, 512>>>(k, Wk, gk, E_, E_, E_, E_, 1.0f, bk);
    gemm_mma<128, 0><<<gproj, 512>>>(v, Wv, gv, E_, E_, E_, E_, 1.0f, bv);

    // 3b) transpose V projection per (b,c) so ctx's B operand is K-major
    transpose512<<<dim3(16, 16, B_ * C_), dim3(32, 8)>>>(gv, gvt);

    // 4) scores = (Q @ K^T) / 8 per (b,h,c)
    dim3 gsc(S_ / 128, S_ / TBM, B_ * H_ * C_);
    gemm_mma<128, 1><<<gsc, 512>>>(gq, gk, attn, E_, E_, S_, HD_, 0.125f, nullptr);

    // 5) softmax over rows of 512, in place
    softmax_rows<<<(B_ * H_ * C_ * S_) / 8, 256>>>(attn);

    // 6) context = attn @ V (heads merged into (b,c,s,E))
    dim3 gcx(1, S_ / TBM, B_ * H_ * C_);
    gemm_mma<64, 2><<<gcx, 256>>>(attn, gvt, gctx, S_, S_, E_, S_, 1.0f, nullptr);

    // 7) output projection
    gemm_mma<128, 0><<<gproj, 512>>>(gctx, Wo, out, E_, E_, E_, E_, 1.0f, bo);
}

// round 17
// speedup vs baseline: 1.0004x; 1.0004x over previous
#include <cuda_runtime.h>
#include <cstddef>
#include <cstdint>

// Problem constants
constexpr int B_ = 4, C_ = 16, S_ = 512, E_ = 512, H_ = 8, HD_ = 64;
constexpr int TOKENS_ = B_ * C_ * S_;                         // 32768
constexpr size_t OUT_ELEMS  = (size_t)TOKENS_ * E_;           // 16,777,216
constexpr size_t ATTN_ELEMS = (size_t)B_ * H_ * C_ * S_ * S_; // 134,217,728

// ---------------------------------------------------------------------------
// Scratch (__device__ globals: allocation APIs are banned)
// ---------------------------------------------------------------------------
__device__ __align__(128) float g_q[OUT_ELEMS];
__device__ __align__(128) float g_k[OUT_ELEMS];
__device__ __align__(128) float g_v[OUT_ELEMS];
__device__ __align__(128) float g_vt[OUT_ELEMS];   // per-(b,c) transposed V proj
__device__ __align__(128) float g_ctx[OUT_ELEMS];
__device__ __align__(128) float g_attn_fb[ATTN_ELEMS];

// ---------------------------------------------------------------------------
// tf32 helpers (baseline PTX, valid for sm_103 family target)
// ---------------------------------------------------------------------------
__device__ __forceinline__ float to_tf32(float x) {
    float r;
    asm("cvt.rna.tf32.f32 %0, %1;" : "=f"(r) : "f"(x));
    return r;
}
__device__ __forceinline__ float4 tf32x4(float4 v) {
    v.x = to_tf32(v.x); v.y = to_tf32(v.y);
    v.z = to_tf32(v.z); v.w = to_tf32(v.w);
    return v;
}
__device__ __forceinline__ void mma_tf32(float* c, const uint32_t* a, const uint32_t* b) {
    asm volatile(
        "mma.sync.aligned.m16n8k8.row.col.f32.tf32.tf32.f32 "
        "{%0,%1,%2,%3}, {%4,%5,%6,%7}, {%8,%9}, {%0,%1,%2,%3};"
        : "+f"(c[0]), "+f"(c[1]), "+f"(c[2]), "+f"(c[3])
        : "r"(a[0]), "r"(a[1]), "r"(a[2]), "r"(a[3]), "r"(b[0]), "r"(b[1]));
}

// ---------------------------------------------------------------------------
// tf32 mma.sync GEMM (TN): C[M,N] = alpha * A[M,K] @ B[N,K]^T (+ bias[N])
// BM=128, BK=16. BN_=128 -> 512 threads (4x4 warps); BN_=64 -> 256 (4x2).
// Warp tile 32x32 = 2x4 m16n8k8 tiles. Register-prefetch double buffering.
// MODE 0: plain. MODE 1: scores (z=(b*H+h)*C+c head slice of Q/K, out z*S*S).
// MODE 2: ctx (A = attn slab z, B = transposed-V head slice, out head slice).
// ---------------------------------------------------------------------------
constexpr int TBM = 128, TBK = 16;

template <int BN_, int MODE>
__global__ void __launch_bounds__((BN_ == 128) ? 512 : 256)
gemm_mma(const float* __restrict__ Ag, const float* __restrict__ Bg,
         float* __restrict__ Cg, int lda, int ldb, int ldc, int K,
         float alpha, const float* __restrict__ bias)
{
    constexpr int NTH     = (BN_ == 128) ? 512 : 256;
    constexpr int WARPS_N = BN_ / 32;                       // 4 or 2
    constexpr int NLD_A   = (TBM * TBK / 4) / NTH;          // 1 or 2
    constexpr int NLD_B   = (BN_ * TBK / 4) / NTH;          // 1

    __shared__ float As[TBK][TBM + 4];   // [k][m], pitch 132
    __shared__ float Bs[TBK][BN_ + 4];   // [k][n]

    const float* A  = Ag;
    const float* Bm = Bg;
    float* Cp = Cg;
    if (MODE == 1) {
        int z = blockIdx.z;
        int c = z % C_, h = (z / C_) % H_, b = z / (C_ * H_);
        size_t off = ((size_t)(b * C_ + c) * S_) * E_ + (size_t)h * HD_;
        A = Ag + off; Bm = Bg + off;
        Cp = Cg + (size_t)z * S_ * S_;
    }
    if (MODE == 2) {
        int z = blockIdx.z;
        int c = z % C_, h = (z / C_) % H_, b = z / (C_ * H_);
        A  = Ag + (size_t)z * S_ * S_;
        Bm = Bg + ((size_t)(b * C_ + c) * E_ + (size_t)h * HD_) * S_;
        Cp = Cg + (size_t)(b * C_ + c) * S_ * E_ + (size_t)h * HD_;
    }

    const int tid  = threadIdx.x;
    const int wid  = tid >> 5;
    const int lane = tid & 31;
    const int gid  = lane >> 2;     // group of 4
    const int tg   = lane & 3;      // thread in group

    const int warp_m = wid / WARPS_N;   // 0..3
    const int warp_n = wid % WARPS_N;   // 0..WARPS_N-1
    const int wm0 = warp_m * 32;
    const int wn0 = warp_n * 32;

    const int bm = blockIdx.y * TBM;
    const int bn = blockIdx.x * BN_;

    // Global tile-load plan: idx -> row = idx/4, k-chunk = idx%4 (float4)
    const float* pAg[NLD_A]; int arow[NLD_A], ak4[NLD_A];
#pragma unroll
    for (int j = 0; j < NLD_A; j++) {
        int idx = j * NTH + tid;
        arow[j] = idx >> 2; ak4[j] = idx & 3;
        pAg[j] = A + (size_t)(bm + arow[j]) * lda + ak4[j] * 4;
    }
    const float* pBg[NLD_B]; int brow[NLD_B], bk4[NLD_B];
#pragma unroll
    for (int j = 0; j < NLD_B; j++) {
        int idx = j * NTH + tid;
        brow[j] = idx >> 2; bk4[j] = idx & 3;
        pBg[j] = Bm + (size_t)(bn + brow[j]) * ldb + bk4[j] * 4;
    }

    float acc[2][4][4];
#pragma unroll
    for (int mt = 0; mt < 2; mt++)
#pragma unroll
        for (int nt = 0; nt < 4; nt++)
#pragma unroll
            for (int r = 0; r < 4; r++) acc[mt][nt][r] = 0.0f;

    float4 ra[NLD_A], rb[NLD_B];
#pragma unroll
    for (int j = 0; j < NLD_A; j++) ra[j] = *(const float4*)pAg[j];
#pragma unroll
    for (int j = 0; j < NLD_B; j++) rb[j] = *(const float4*)pBg[j];

    const int nslab = K / TBK;
    for (int kt = 0; kt < nslab; kt++) {
        // transposed stores with tf32 rounding
#pragma unroll
        for (int j = 0; j < NLD_A; j++) {
            float4 v = tf32x4(ra[j]);
            int kk = ak4[j] * 4, m = arow[j];
            As[kk + 0][m] = v.x; As[kk + 1][m] = v.y;
            As[kk + 2][m] = v.z; As[kk + 3][m] = v.w;
        }
#pragma unroll
        for (int j = 0; j < NLD_B; j++) {
            float4 v = tf32x4(rb[j]);
            int kk = bk4[j] * 4, n = brow[j];
            Bs[kk + 0][n] = v.x; Bs[kk + 1][n] = v.y;
            Bs[kk + 2][n] = v.z; Bs[kk + 3][n] = v.w;
        }
        __syncthreads();

        if (kt + 1 < nslab) {   // prefetch next slab into registers
#pragma unroll
            for (int j = 0; j < NLD_A; j++)
                ra[j] = *(const float4*)(pAg[j] + (size_t)(kt + 1) * TBK);
#pragma unroll
            for (int j = 0; j < NLD_B; j++)
                rb[j] = *(const float4*)(pBg[j] + (size_t)(kt + 1) * TBK);
        }

#pragma unroll
        for (int ks = 0; ks < TBK; ks += 8) {
            uint32_t af[2][4];
#pragma unroll
            for (int mt = 0; mt < 2; mt++) {
                int m0 = wm0 + mt * 16 + gid;
                af[mt][0] = __float_as_uint(As[ks + tg][m0]);
                af[mt][1] = __float_as_uint(As[ks + tg][m0 + 8]);
                af[mt][2] = __float_as_uint(As[ks + tg + 4][m0]);
                af[mt][3] = __float_as_uint(As[ks + tg + 4][m0 + 8]);
            }
            uint32_t bf[4][2];
#pragma unroll
            for (int nt = 0; nt < 4; nt++) {
                int n0 = wn0 + nt * 8 + gid;
                bf[nt][0] = __float_as_uint(Bs[ks + tg][n0]);
                bf[nt][1] = __float_as_uint(Bs[ks + tg + 4][n0]);
            }
#pragma unroll
            for (int mt = 0; mt < 2; mt++)
#pragma unroll
                for (int nt = 0; nt < 4; nt++)
                    mma_tf32(acc[mt][nt], af[mt], bf[nt]);
        }
        __syncthreads();
    }

    // Epilogue: c0/c1 -> (row, 2tg), (row, 2tg+1); c2/c3 -> row+8
#pragma unroll
    for (int mt = 0; mt < 2; mt++) {
#pragma unroll
        for (int nt = 0; nt < 4; nt++) {
            int row = bm + wm0 + mt * 16 + gid;
            int col = bn + wn0 + nt * 8 + tg * 2;
            float2 bb = make_float2(0.0f, 0.0f);
            if (bias) bb = *(const float2*)(bias + col);
            float2 v0, v1;
            v0.x = acc[mt][nt][0] * alpha + bb.x;
            v0.y = acc[mt][nt][1] * alpha + bb.y;
            v1.x = acc[mt][nt][2] * alpha + bb.x;
            v1.y = acc[mt][nt][3] * alpha + bb.y;
            *(float2*)(Cp + (size_t)row * ldc + col)       = v0;
            *(float2*)(Cp + (size_t)(row + 8) * ldc + col) = v1;
        }
    }
}

// ---------------------------------------------------------------------------
// Per-(b,c) 512x512 transpose of the V projection (token-major -> [e][s])
// so the ctx GEMM sees a K-major (TN) B operand.
// ---------------------------------------------------------------------------
__global__ void transpose512(const float* __restrict__ in, float* __restrict__ out)
{
    __shared__ float t[32][33];
    const size_t base = (size_t)blockIdx.z * 512 * 512;
    const float* I = in + base;
    float* O = out + base;
    int x = blockIdx.x * 32 + threadIdx.x;   // e
    int y = blockIdx.y * 32 + threadIdx.y;   // s
#pragma unroll
    for (int i = 0; i < 32; i += 8)
        t[threadIdx.y + i][threadIdx.x] = I[(size_t)(y + i) * 512 + x];
    __syncthreads();
    int x2 = blockIdx.y * 32 + threadIdx.x;  // s
    int y2 = blockIdx.x * 32 + threadIdx.y;  // e
#pragma unroll
    for (int i = 0; i < 32; i += 8)
        O[(size_t)(y2 + i) * 512 + x2] = t[threadIdx.x][threadIdx.y + i];
}

// ---------------------------------------------------------------------------
// Row softmax, in place, rows of exactly 512 floats. One warp per row.
// ---------------------------------------------------------------------------
__global__ void softmax_rows(float* __restrict__ attn)
{
    const int warp = (blockIdx.x * blockDim.x + threadIdx.x) >> 5;
    const int lane = threadIdx.x & 31;
    float* row = attn + (size_t)warp * S_;

    float4 v[4];
    float mx = -3.0e38f;
#pragma unroll
    for (int i = 0; i < 4; i++) {
        v[i] = *(const float4*)(row + (size_t)(lane + 32 * i) * 4);
        mx = fmaxf(mx, fmaxf(fmaxf(v[i].x, v[i].y), fmaxf(v[i].z, v[i].w)));
    }
#pragma unroll
    for (int s = 16; s > 0; s >>= 1)
        mx = fmaxf(mx, __shfl_xor_sync(0xffffffffu, mx, s));

    float sum = 0.0f;
#pragma unroll
    for (int i = 0; i < 4; i++) {
        v[i].x = __expf(v[i].x - mx); v[i].y = __expf(v[i].y - mx);
        v[i].z = __expf(v[i].z - mx); v[i].w = __expf(v[i].w - mx);
        sum += v[i].x + v[i].y + v[i].z + v[i].w;
    }
#pragma unroll
    for (int s = 16; s > 0; s >>= 1)
        sum += __shfl_xor_sync(0xffffffffu, sum, s);

    const float inv = 1.0f / sum;
#pragma unroll
    for (int i = 0; i < 4; i++) {
        v[i].x *= inv; v[i].y *= inv; v[i].z *= inv; v[i].w *= inv;
        *(float4*)(row + (size_t)(lane + 32 * i) * 4) = v[i];
    }
}

// ---------------------------------------------------------------------------
// Launch (graph-capturable: kernel launches only)
// ---------------------------------------------------------------------------
extern "C" void kernel_launch(void* const* d_in, const int* in_sizes, int n_in,
                              void* d_out, int out_size)
{
    const float* q  = (const float*)d_in[0];
    const float* k  = (const float*)d_in[1];
    const float* v  = (const float*)d_in[2];
    const float* Wq = (const float*)d_in[3];
    const float* bq = (const float*)d_in[4];
    const float* Wk = (const float*)d_in[5];
    const float* bk = (const float*)d_in[6];
    const float* Wv = (const float*)d_in[7];
    const float* bv = (const float*)d_in[8];
    const float* Wo = (const float*)d_in[9];
    const float* bo = (const float*)d_in[10];
    float* out = (float*)d_out;

    float *gq, *gk, *gv, *gvt, *gctx, *gfb;
    cudaGetSymbolAddress((void**)&gq,   g_q);
    cudaGetSymbolAddress((void**)&gk,   g_k);
    cudaGetSymbolAddress((void**)&gv,   g_v);
    cudaGetSymbolAddress((void**)&gvt,  g_vt);
    cudaGetSymbolAddress((void**)&gctx, g_ctx);
    cudaGetSymbolAddress((void**)&gfb,  g_attn_fb);

    float* attn = ((size_t)out_size >= OUT_ELEMS + ATTN_ELEMS)
                      ? (out + OUT_ELEMS) : gfb;

    // 1-3) Q/K/V projections: (32768 x 512) = X @ W^T + b
    dim3 gproj(E_ / 128, TOKENS_ / TBM, 1);
    gemm_mma<128, 0><<<gproj, 512>>>(q, Wq, gq, E_, E_, E_, E_, 1.0f, bq);
    gemm_mma<128, 0><<<gproj, 512>>>(k, Wk, gk, E_, E_, E_, E_, 1.0f, bk);
    gemm_mma<128, 0><<<gproj, 512>>>(v, Wv, gv, E_, E_, E_, E_, 1.0f, bv);

    // 3b) transpose V projection per (b,c) so ctx's B operand is K-major
    transpose512<<<dim3(16, 16, B_ * C_), dim3(32, 8)>>>(gv, gvt);

    // 4) scores = (Q @ K^T) / 8 per (b,h,c)
    dim3 gsc(S_ / 128, S_ / TBM, B_ * H_ * C_);
    gemm_mma<128, 1><<<gsc, 512>>>(gq, gk, attn, E_, E_, S_, HD_, 0.125f, nullptr);

    // 5) softmax over rows of 512, in place
    softmax_rows<<<(B_ * H_ * C_ * S_) / 8, 256>>>(attn);

    // 6) context = attn @ V (heads merged into (b,c,s,E))
    dim3 gcx(1, S_ / TBM, B_ * H_ * C_);
    gemm_mma<64, 2><<<gcx, 256>>>(attn, gvt, gctx, S_, S_, E_, S_, 1.0f, nullptr);

    // 7) output projection
    gemm_mma<128, 0><<<gproj, 512>>>(gctx, Wo, out, E_, E_, E_, E_, 1.0f, bo);
}